// round 7
// baseline (speedup 1.0000x reference)
#include <cuda_runtime.h>

// Problem constants
#define M_TOK 256
#define KDIM  1024
#define NDIM  2048
#define NEXP  64
#define TOPKN 8
#define LTOT  (M_TOK * TOPKN)   // 2048 assignments
#define CAP   (LTOT / NEXP)     // 32 per expert (balanced routing)

// GEMM tiling
#define TILE_N   256
#define KB       64
#define BSTRIDE  65             // odd stride -> conflict-free compute b-reads
#define NTHREADS 128
#define SMEM_FLOATS (TILE_N * BSTRIDE + KB * CAP)
#define SMEM_BYTES  (SMEM_FLOATS * 4)

// Routing scratch (no allocations allowed -> device globals)
__device__ int   g_tok[LTOT];   // source token row per sorted slot
__device__ float g_w[LTOT];     // routing weight per sorted slot
__device__ int   g_slot[LTOT];  // output row (flat assignment index) per sorted slot

typedef unsigned long long u64;

__device__ __forceinline__ u64 pack2(float lo, float hi) {
    u64 r; asm("mov.b64 %0, {%1, %2};" : "=l"(r) : "f"(lo), "f"(hi)); return r;
}
__device__ __forceinline__ void unpack2(u64 v, float& lo, float& hi) {
    asm("mov.b64 {%0, %1}, %2;" : "=f"(lo), "=f"(hi) : "l"(v));
}
// Packed dual fp32 FMA (sm_100+; ptxas never auto-generates this -> PTX inline)
__device__ __forceinline__ void fma2(u64& d, u64 a, u64 b) {
    asm("fma.rn.f32x2 %0, %1, %2, %3;" : "=l"(d) : "l"(a), "l"(b), "l"(d));
}

// ---------------------------------------------------------------------------
// Routing: stable compaction by expert id, reproducing jnp.argsort's stable
// order exactly. One warp per expert; ballot + popc keeps source order.
// ---------------------------------------------------------------------------
__global__ void route_kernel(const int* __restrict__ ids,
                             const float* __restrict__ tw) {
    const int e    = blockIdx.x;
    const int lane = threadIdx.x;
    int base = 0;
    for (int i0 = 0; i0 < LTOT; i0 += 32) {
        const int i  = i0 + lane;
        const int id = ids[i];
        const unsigned m = __ballot_sync(0xffffffffu, id == e);
        if (id == e) {
            const int r = __popc(m & ((1u << lane) - 1u));
            const int p = e * CAP + base + r;
            g_tok[p]  = i / TOPKN;
            g_w[p]    = tw[i];
            g_slot[p] = i;
        }
        base += __popc(m);
    }
}

// ---------------------------------------------------------------------------
// Grouped GEMM: per block, one expert x 256-wide N tile.
//   C[32, 256] = A_gathered[32, K] * B[e]^T (+bias) * w, scattered to out.
// 128 threads; each thread: 8 tokens x 8 n = 32 f32x2 accumulators.
//   tn = lane (n = n0 + tn + 32j), tc = warp (tokens 8tc..8tc+7).
// SMEM: Bs[256][65] n-major (b-read bank = (tn+kk)%32: conflict-free),
//       As[64][32] k-major (a-read is a warp-broadcast LDS.64: free).
// ---------------------------------------------------------------------------
__global__ void __launch_bounds__(NTHREADS, 3)
moe_gemm_kernel(const float* __restrict__ A, const float* __restrict__ B,
                const float* __restrict__ bias, float* __restrict__ out) {
    extern __shared__ float smem[];
    float* Bs = smem;                         // [TILE_N][BSTRIDE]
    float* As = smem + TILE_N * BSTRIDE;      // [KB][CAP]

    const int tid = threadIdx.x;
    const int tn  = tid & 31;                 // lane
    const int tc  = tid >> 5;                 // warp 0..3

    const int e  = blockIdx.x >> 3;           // 8 N-tiles per expert
    const int n0 = (blockIdx.x & 7) * TILE_N;

    // A loader mapping: one token row per lane, 4 float4 k-quads per thread
    const int a_c  = tid & 31;
    const int a_q4 = tid >> 5;
    const float* aRow = A + (size_t)g_tok[e * CAP + a_c] * KDIM;

    // B loader mapping: 128B-coalesced LDG.128; scalar STS bank-conflict-free
    const int b_kq = tid & 7;                 // k-quad within first 32
    const int b_nb = tid >> 3;                // 0..15
    const float* bBase = B + ((size_t)e * NDIM + n0) * KDIM;

    u64 acc[4][8];
    #pragma unroll
    for (int p = 0; p < 4; p++)
        #pragma unroll
        for (int j = 0; j < 8; j++) acc[p][j] = 0ull;

    const float* aCompBase = As + 8 * tc;
    const float* bCompBase = Bs + tn * BSTRIDE;

    for (int s = 0; s < KDIM / KB; s++) {
        __syncthreads();                       // protect smem reuse
        const int k0 = s * KB;

        // Stage A tile: As[k][c] (transposed store, lanes hit distinct banks)
        #pragma unroll
        for (int i = 0; i < 4; i++) {
            const int q = a_q4 + 4 * i;        // k-quad 0..15
            float4 v = *(const float4*)(aRow + k0 + 4 * q);
            float* d = As + (4 * q) * CAP + a_c;
            d[0 * CAP] = v.x; d[1 * CAP] = v.y; d[2 * CAP] = v.z; d[3 * CAP] = v.w;
        }
        // Stage B tile: Bs[nn][k] row-major, stride 65
        #pragma unroll
        for (int i = 0; i < 16; i++) {
            const int nn = b_nb + 16 * i;
            const float* br = bBase + (size_t)nn * KDIM + k0;
            float4 va = *(const float4*)(br + 4 * b_kq);
            float4 vb = *(const float4*)(br + 32 + 4 * b_kq);
            float* d = Bs + nn * BSTRIDE + 4 * b_kq;
            d[0]  = va.x; d[1]  = va.y; d[2]  = va.z; d[3]  = va.w;
            d[32] = vb.x; d[33] = vb.y; d[34] = vb.z; d[35] = vb.w;
        }
        __syncthreads();

        // Compute: per k-step 12 LDS + 8 packs + 32 FFMA2 (FMA-pipe-bound)
        #pragma unroll 16
        for (int kk = 0; kk < KB; kk++) {
            const float* ar = aCompBase + kk * CAP;
            const u64 ap0 = *(const u64*)(ar + 0);  // token pair (8tc+0, 8tc+1)
            const u64 ap1 = *(const u64*)(ar + 2);
            const u64 ap2 = *(const u64*)(ar + 4);
            const u64 ap3 = *(const u64*)(ar + 6);
            #pragma unroll
            for (int j = 0; j < 8; j++) {
                const float b = bCompBase[32 * j * BSTRIDE + kk];
                const u64 bb = pack2(b, b);
                fma2(acc[0][j], ap0, bb);
                fma2(acc[1][j], ap1, bb);
                fma2(acc[2][j], ap2, bb);
                fma2(acc[3][j], ap3, bb);
            }
        }
    }

    // Epilogue: (acc + bias[e,n]) * w[slot], scatter to out[slot, n]
    int   slot[8];
    float w8[8];
    #pragma unroll
    for (int t = 0; t < 8; t++) {
        slot[t] = g_slot[e * CAP + 8 * tc + t];
        w8[t]   = g_w  [e * CAP + 8 * tc + t];
    }
    float bv[8];
    #pragma unroll
    for (int j = 0; j < 8; j++)
        bv[j] = bias[e * NDIM + n0 + tn + 32 * j];

    #pragma unroll
    for (int p = 0; p < 4; p++) {
        #pragma unroll
        for (int j = 0; j < 8; j++) {
            float lo, hi;
            unpack2(acc[p][j], lo, hi);
            const int n = n0 + tn + 32 * j;
            out[(size_t)slot[2 * p]     * NDIM + n] = (lo + bv[j]) * w8[2 * p];
            out[(size_t)slot[2 * p + 1] * NDIM + n] = (hi + bv[j]) * w8[2 * p + 1];
        }
    }
}

extern "C" void kernel_launch(void* const* d_in, const int* in_sizes, int n_in,
                              void* d_out, int out_size) {
    const float* A    = (const float*)d_in[0];   // [256, 1024] f32
    const float* B    = (const float*)d_in[1];   // [64, 2048, 1024] f32
    const float* bias = (const float*)d_in[2];   // [64, 2048] f32
    const float* tw   = (const float*)d_in[3];   // [256, 8] f32
    const int*   ids  = (const int*)d_in[4];     // [256, 8] i32
    float* out = (float*)d_out;                  // [256, 8, 2048] f32

    (void)in_sizes; (void)n_in; (void)out_size;

    cudaFuncSetAttribute(moe_gemm_kernel,
                         cudaFuncAttributeMaxDynamicSharedMemorySize, SMEM_BYTES);

    route_kernel<<<NEXP, 32>>>(ids, tw);
    moe_gemm_kernel<<<NEXP * (NDIM / TILE_N), NTHREADS, SMEM_BYTES>>>(A, B, bias, out);
}

// round 9
// speedup vs baseline: 1.3784x; 1.3784x over previous
#include <cuda_runtime.h>
#include <cstdint>

// Problem constants
#define M_TOK 256
#define KDIM  1024
#define NDIM  2048
#define NEXP  64
#define TOPKN 8
#define LTOT  (M_TOK * TOPKN)   // 2048 assignments
#define CAP   (LTOT / NEXP)     // 32 per expert (balanced routing)

// GEMM tiling
#define TILE_N   256
#define KB       32             // k-slab per stage (32 stages)
#define NSTAGE   (KDIM / KB)
#define NTHREADS 128
#define B_FLOATS (TILE_N * KB)          // 8192 floats / 32KB per buffer
#define A_FLOATS (KB * CAP)             // 1024 floats / 4KB per buffer
#define SMEM_BYTES ((2 * B_FLOATS + 2 * A_FLOATS) * 4)   // 72KB -> 3 blocks/SM

// Routing scratch (no allocations allowed -> device globals)
__device__ int   g_tok[LTOT];   // source token row per sorted slot
__device__ float g_w[LTOT];     // routing weight per sorted slot
__device__ int   g_slot[LTOT];  // output row (flat assignment index) per sorted slot

typedef unsigned long long u64;

__device__ __forceinline__ u64 pack2(float lo, float hi) {
    u64 r; asm("mov.b64 %0, {%1, %2};" : "=l"(r) : "f"(lo), "f"(hi)); return r;
}
__device__ __forceinline__ void unpack2(u64 v, float& lo, float& hi) {
    asm("mov.b64 {%0, %1}, %2;" : "=f"(lo), "=f"(hi) : "l"(v));
}
// Packed dual fp32 FMA (sm_100+; PTX-only, ptxas never auto-generates)
__device__ __forceinline__ void fma2(u64& d, u64 a, u64 b) {
    asm("fma.rn.f32x2 %0, %1, %2, %3;" : "=l"(d) : "l"(a), "l"(b), "l"(d));
}
__device__ __forceinline__ void cp_async16(uint32_t dst, const float* src) {
    asm volatile("cp.async.cg.shared.global [%0], [%1], 16;" :: "r"(dst), "l"(src));
}
__device__ __forceinline__ void cp_commit() {
    asm volatile("cp.async.commit_group;");
}
__device__ __forceinline__ void cp_wait_all() {
    asm volatile("cp.async.wait_group 0;");
}

// ---------------------------------------------------------------------------
// Routing: stable compaction by expert id, reproducing jnp.argsort's stable
// order exactly. One warp per expert; ballot + popc keeps source order.
// ---------------------------------------------------------------------------
__global__ void route_kernel(const int* __restrict__ ids,
                             const float* __restrict__ tw) {
    const int e    = blockIdx.x;
    const int lane = threadIdx.x;
    int base = 0;
    for (int i0 = 0; i0 < LTOT; i0 += 32) {
        const int i  = i0 + lane;
        const int id = ids[i];
        const unsigned m = __ballot_sync(0xffffffffu, id == e);
        if (id == e) {
            const int r = __popc(m & ((1u << lane) - 1u));
            const int p = e * CAP + base + r;
            g_tok[p]  = i / TOPKN;
            g_w[p]    = tw[i];
            g_slot[p] = i;
        }
        base += __popc(m);
    }
}

// ---------------------------------------------------------------------------
// Grouped GEMM, cp.async double-buffered.
//   Block: one expert x 256-wide N tile; 128 threads; per thread 8 tok x 8 n
//   as 32 f32x2 accumulators (token pairs).
// B smem layout (per stage): element B[nn][4*kq+t] stored at FLOAT offset
//   32*nn + 4*(kq ^ (nn&7)) + t   (16B-chunk XOR swizzle).
// Compute b-read for nn = tn+32j: float4 at 32*tn + 1024*j + 4*(kq^t7)
//   -> per 8-lane phase start banks {0,4,...,28}, each lane spans 4 banks:
//   all 32 banks exactly once -> conflict-free LDS.128.
// A smem: As[k][tok] (stride 32); compute a-read is warp-broadcast LDS.128.
// ---------------------------------------------------------------------------
__global__ void __launch_bounds__(NTHREADS, 3)
moe_gemm_kernel(const float* __restrict__ A, const float* __restrict__ B,
                const float* __restrict__ bias, float* __restrict__ out) {
    extern __shared__ float smem[];
    float* Bs = smem;                          // [2][B_FLOATS]
    float* As = smem + 2 * B_FLOATS;           // [2][A_FLOATS]

    const int tid = threadIdx.x;
    const int tn  = tid & 31;                  // lane
    const int tc  = tid >> 5;                  // warp 0..3
    const int t7  = tn & 7;

    const int e  = blockIdx.x >> 3;            // 8 N-tiles per expert
    const int n0 = (blockIdx.x & 7) * TILE_N;

    // A loader mapping: lane a_c owns token a_c; a_q4 selects k-subchunk of 8
    const int a_c  = tid & 31;
    const int a_q4 = tid >> 5;
    const float* aRow = A + (size_t)g_tok[e * CAP + a_c] * KDIM;

    // B loader mapping: thread owns 16 chunks (16 rows apart), fixed kq chunk
    const int b_kq  = tid & 7;                 // chunk column 0..7
    const int b_nn0 = tid >> 3;                // row 0..15
    const int b_dx  = b_kq ^ (b_nn0 & 7);      // swizzled chunk col (16i keeps nn&7)
    const float* bBase = B + ((size_t)e * NDIM + n0) * KDIM;

    uint32_t bsAddr[2];
    bsAddr[0] = (uint32_t)__cvta_generic_to_shared(Bs);
    bsAddr[1] = (uint32_t)__cvta_generic_to_shared(Bs + B_FLOATS);

    u64 acc[4][8];
    #pragma unroll
    for (int p = 0; p < 4; p++)
        #pragma unroll
        for (int j = 0; j < 8; j++) acc[p][j] = 0ull;

    // ---- prologue: issue stage 0 B copy, load stage 0 A into regs ----
    {
        const uint32_t dst = bsAddr[0];
        #pragma unroll
        for (int i = 0; i < 16; i++) {
            const int nn = b_nn0 + 16 * i;
            cp_async16(dst + 4u * (32 * nn + 4 * b_dx),
                       bBase + (size_t)nn * KDIM + 4 * b_kq);
        }
        cp_commit();
    }
    float4 av0 = *(const float4*)(aRow + 8 * a_q4);
    float4 av1 = *(const float4*)(aRow + 8 * a_q4 + 4);

    for (int s = 0; s < NSTAGE; s++) {
        const int cur = s & 1;
        const int nxt = cur ^ 1;

        cp_wait_all();                         // B_s landed (this thread's copies)
        // stage A_s regs -> As[cur] (k-major; bank = a_c, conflict-free)
        {
            float* d = As + cur * A_FLOATS + (8 * a_q4) * CAP + a_c;
            d[0 * CAP] = av0.x; d[1 * CAP] = av0.y;
            d[2 * CAP] = av0.z; d[3 * CAP] = av0.w;
            d[4 * CAP] = av1.x; d[5 * CAP] = av1.y;
            d[6 * CAP] = av1.z; d[7 * CAP] = av1.w;
        }
        __syncthreads();                       // tiles visible; prev compute done

        if (s + 1 < NSTAGE) {                  // prefetch stage s+1 (overlaps compute)
            const int k0n = (s + 1) * KB;
            const uint32_t dst = bsAddr[nxt];
            #pragma unroll
            for (int i = 0; i < 16; i++) {
                const int nn = b_nn0 + 16 * i;
                cp_async16(dst + 4u * (32 * nn + 4 * b_dx),
                           bBase + (size_t)nn * KDIM + k0n + 4 * b_kq);
            }
            cp_commit();
            av0 = *(const float4*)(aRow + k0n + 8 * a_q4);
            av1 = *(const float4*)(aRow + k0n + 8 * a_q4 + 4);
        }

        // ---- compute stage s ----
        const float* BsC = Bs + cur * B_FLOATS;
        const float* AsC = As + cur * A_FLOATS;
        #pragma unroll 2
        for (int kq = 0; kq < 8; kq++) {
            // b: 8 x LDS.128 (4 k-steps each), swizzle-conflict-free
            const float* pB = BsC + 32 * tn + 4 * (kq ^ t7);   // FIXED: 32*tn (floats), was 8*tn
            float4 b4[8];
            #pragma unroll
            for (int j = 0; j < 8; j++)
                b4[j] = *(const float4*)(pB + 1024 * j);

            const float* pA = AsC + 128 * kq + 8 * tc;
            #pragma unroll
            for (int kk2 = 0; kk2 < 4; kk2++) {
                // a: warp-broadcast LDS.128 -> 2 token-pair u64s each
                ulonglong2 aA = *(const ulonglong2*)(pA + 32 * kk2);
                ulonglong2 aB = *(const ulonglong2*)(pA + 32 * kk2 + 4);
                #pragma unroll
                for (int j = 0; j < 8; j++) {
                    const float* bp = (const float*)&b4[j];
                    const float bs = bp[kk2];
                    const u64 bb = pack2(bs, bs);
                    fma2(acc[0][j], aA.x, bb);
                    fma2(acc[1][j], aA.y, bb);
                    fma2(acc[2][j], aB.x, bb);
                    fma2(acc[3][j], aB.y, bb);
                }
            }
        }
    }

    // ---- epilogue: (acc + bias[e,n]) * w[slot], scatter to out[slot, n] ----
    int   slot[8];
    float w8[8];
    #pragma unroll
    for (int t = 0; t < 8; t++) {
        slot[t] = g_slot[e * CAP + 8 * tc + t];
        w8[t]   = g_w  [e * CAP + 8 * tc + t];
    }
    float bv[8];
    #pragma unroll
    for (int j = 0; j < 8; j++)
        bv[j] = bias[e * NDIM + n0 + tn + 32 * j];

    #pragma unroll
    for (int p = 0; p < 4; p++) {
        #pragma unroll
        for (int j = 0; j < 8; j++) {
            float lo, hi;
            unpack2(acc[p][j], lo, hi);
            const int n = n0 + tn + 32 * j;
            out[(size_t)slot[2 * p]     * NDIM + n] = (lo + bv[j]) * w8[2 * p];
            out[(size_t)slot[2 * p + 1] * NDIM + n] = (hi + bv[j]) * w8[2 * p + 1];
        }
    }
}

extern "C" void kernel_launch(void* const* d_in, const int* in_sizes, int n_in,
                              void* d_out, int out_size) {
    const float* A    = (const float*)d_in[0];   // [256, 1024] f32
    const float* B    = (const float*)d_in[1];   // [64, 2048, 1024] f32
    const float* bias = (const float*)d_in[2];   // [64, 2048] f32
    const float* tw   = (const float*)d_in[3];   // [256, 8] f32
    const int*   ids  = (const int*)d_in[4];     // [256, 8] i32
    float* out = (float*)d_out;                  // [256, 8, 2048] f32

    (void)in_sizes; (void)n_in; (void)out_size;

    cudaFuncSetAttribute(moe_gemm_kernel,
                         cudaFuncAttributeMaxDynamicSharedMemorySize, SMEM_BYTES);

    route_kernel<<<NEXP, 32>>>(ids, tw);
    moe_gemm_kernel<<<NEXP * (NDIM / TILE_N), NTHREADS, SMEM_BYTES>>>(A, B, bias, out);
}

// round 11
// speedup vs baseline: 1.4477x; 1.0503x over previous
#include <cuda_runtime.h>
#include <cstdint>

// Problem constants
#define M_TOK 256
#define KDIM  1024
#define NDIM  2048
#define NEXP  64
#define TOPKN 8
#define LTOT  (M_TOK * TOPKN)   // 2048 assignments
#define CAP   (LTOT / NEXP)     // 32 per expert (balanced routing)

// GEMM tiling
#define TILE_N   128
#define NTILES   (NDIM / TILE_N)        // 16 N-tiles per expert
#define KB       32                     // k-slab per stage (32 stages)
#define NSTAGE   (KDIM / KB)
#define NTHREADS 128
#define B_FLOATS (TILE_N * KB)          // 4096 floats / 16KB per buffer
#define A_FLOATS (KB * CAP)             // 1024 floats / 4KB per buffer
#define SMEM_BYTES ((2 * B_FLOATS + 2 * A_FLOATS) * 4)   // 40KB -> 5 blocks/SM

// Routing scratch (no allocations allowed -> device globals)
__device__ int   g_tok[LTOT];   // source token row per sorted slot
__device__ float g_w[LTOT];     // routing weight per sorted slot
__device__ int   g_slot[LTOT];  // output row (flat assignment index) per sorted slot

typedef unsigned long long u64;

__device__ __forceinline__ u64 pack2(float lo, float hi) {
    u64 r; asm("mov.b64 %0, {%1, %2};" : "=l"(r) : "f"(lo), "f"(hi)); return r;
}
__device__ __forceinline__ void unpack2(u64 v, float& lo, float& hi) {
    asm("mov.b64 {%0, %1}, %2;" : "=f"(lo), "=f"(hi) : "l"(v));
}
// Packed dual fp32 FMA (sm_100+; PTX-only, ptxas never auto-generates)
__device__ __forceinline__ void fma2(u64& d, u64 a, u64 b) {
    asm("fma.rn.f32x2 %0, %1, %2, %3;" : "=l"(d) : "l"(a), "l"(b), "l"(d));
}
__device__ __forceinline__ void cp_async16(uint32_t dst, const float* src) {
    asm volatile("cp.async.cg.shared.global [%0], [%1], 16;" :: "r"(dst), "l"(src));
}
__device__ __forceinline__ void cp_commit() {
    asm volatile("cp.async.commit_group;");
}
__device__ __forceinline__ void cp_wait_all() {
    asm volatile("cp.async.wait_group 0;");
}

// ---------------------------------------------------------------------------
// Routing: stable compaction by expert id, reproducing jnp.argsort's stable
// order exactly. One warp per expert; ballot + popc keeps source order.
// ---------------------------------------------------------------------------
__global__ void route_kernel(const int* __restrict__ ids,
                             const float* __restrict__ tw) {
    const int e    = blockIdx.x;
    const int lane = threadIdx.x;
    int base = 0;
    for (int i0 = 0; i0 < LTOT; i0 += 32) {
        const int i  = i0 + lane;
        const int id = ids[i];
        const unsigned m = __ballot_sync(0xffffffffu, id == e);
        if (id == e) {
            const int r = __popc(m & ((1u << lane) - 1u));
            const int p = e * CAP + base + r;
            g_tok[p]  = i / TOPKN;
            g_w[p]    = tw[i];
            g_slot[p] = i;
        }
        base += __popc(m);
    }
}

// ---------------------------------------------------------------------------
// Grouped GEMM, cp.async double-buffered, occupancy-tuned.
//   Block: one expert x 128-wide N tile; 128 threads; per thread 8 tok x 4 n
//   as 16 f32x2 accumulators (token pairs). 5 blocks/SM (~31% occ).
// B smem layout (per stage): element B[nn][4*kq+t] at FLOAT offset
//   32*nn + 4*(kq ^ (nn&7)) + t   (16B-chunk XOR swizzle).
// Compute b-read for nn = tn+32j: float4 at 32*tn + 1024*j + 4*(kq^t7)
//   -> per 8-lane phase start banks {0,4,...,28}, each lane spans 4 banks:
//   all 32 banks exactly once -> conflict-free LDS.128.
// A smem: As[k][tok] (stride 32); compute a-read is warp-broadcast LDS.128.
// ---------------------------------------------------------------------------
__global__ void __launch_bounds__(NTHREADS, 5)
moe_gemm_kernel(const float* __restrict__ A, const float* __restrict__ B,
                const float* __restrict__ bias, float* __restrict__ out) {
    extern __shared__ float smem[];
    float* Bs = smem;                          // [2][B_FLOATS]
    float* As = smem + 2 * B_FLOATS;           // [2][A_FLOATS]

    const int tid = threadIdx.x;
    const int tn  = tid & 31;                  // lane
    const int tc  = tid >> 5;                  // warp 0..3
    const int t7  = tn & 7;

    const int e  = blockIdx.x >> 4;            // 16 N-tiles per expert
    const int n0 = (blockIdx.x & 15) * TILE_N;

    // A loader mapping: lane a_c owns token a_c; a_q4 selects k-subchunk of 8
    const int a_c  = tid & 31;
    const int a_q4 = tid >> 5;
    const float* aRow = A + (size_t)g_tok[e * CAP + a_c] * KDIM;

    // B loader mapping: thread owns 8 chunks (rows 16 apart), fixed kq chunk
    const int b_kq  = tid & 7;                 // chunk column 0..7
    const int b_nn0 = tid >> 3;                // row 0..15
    const int b_dx  = b_kq ^ (b_nn0 & 7);      // swizzled chunk col (16i keeps nn&7)
    const float* bBase = B + ((size_t)e * NDIM + n0) * KDIM;

    uint32_t bsAddr[2];
    bsAddr[0] = (uint32_t)__cvta_generic_to_shared(Bs);
    bsAddr[1] = (uint32_t)__cvta_generic_to_shared(Bs + B_FLOATS);

    u64 acc[4][4];
    #pragma unroll
    for (int p = 0; p < 4; p++)
        #pragma unroll
        for (int j = 0; j < 4; j++) acc[p][j] = 0ull;

    // ---- prologue: issue stage 0 B copy, load stage 0 A into regs ----
    {
        const uint32_t dst = bsAddr[0];
        #pragma unroll
        for (int i = 0; i < 8; i++) {
            const int nn = b_nn0 + 16 * i;
            cp_async16(dst + 4u * (32 * nn + 4 * b_dx),
                       bBase + (size_t)nn * KDIM + 4 * b_kq);
        }
        cp_commit();
    }
    float4 av0 = *(const float4*)(aRow + 8 * a_q4);
    float4 av1 = *(const float4*)(aRow + 8 * a_q4 + 4);

    for (int s = 0; s < NSTAGE; s++) {
        const int cur = s & 1;
        const int nxt = cur ^ 1;

        cp_wait_all();                         // B_s landed
        // stage A_s regs -> As[cur] (k-major; bank = a_c, conflict-free)
        {
            float* d = As + cur * A_FLOATS + (8 * a_q4) * CAP + a_c;
            d[0 * CAP] = av0.x; d[1 * CAP] = av0.y;
            d[2 * CAP] = av0.z; d[3 * CAP] = av0.w;
            d[4 * CAP] = av1.x; d[5 * CAP] = av1.y;
            d[6 * CAP] = av1.z; d[7 * CAP] = av1.w;
        }
        __syncthreads();                       // tiles visible; prev compute done

        if (s + 1 < NSTAGE) {                  // prefetch stage s+1 (overlaps compute)
            const int k0n = (s + 1) * KB;
            const uint32_t dst = bsAddr[nxt];
            #pragma unroll
            for (int i = 0; i < 8; i++) {
                const int nn = b_nn0 + 16 * i;
                cp_async16(dst + 4u * (32 * nn + 4 * b_dx),
                           bBase + (size_t)nn * KDIM + k0n + 4 * b_kq);
            }
            cp_commit();
            av0 = *(const float4*)(aRow + k0n + 8 * a_q4);
            av1 = *(const float4*)(aRow + k0n + 8 * a_q4 + 4);
        }

        // ---- compute stage s ----
        const float* BsC = Bs + cur * B_FLOATS;
        const float* AsC = As + cur * A_FLOATS;
        #pragma unroll 2
        for (int kq = 0; kq < 8; kq++) {
            // b: 4 x LDS.128 (4 k-steps each), swizzle-conflict-free
            const float* pB = BsC + 32 * tn + 4 * (kq ^ t7);
            float4 b4[4];
            #pragma unroll
            for (int j = 0; j < 4; j++)
                b4[j] = *(const float4*)(pB + 1024 * j);

            const float* pA = AsC + 128 * kq + 8 * tc;
            #pragma unroll
            for (int kk2 = 0; kk2 < 4; kk2++) {
                // a: warp-broadcast LDS.128 -> 2 token-pair u64s each
                ulonglong2 aA = *(const ulonglong2*)(pA + 32 * kk2);
                ulonglong2 aB = *(const ulonglong2*)(pA + 32 * kk2 + 4);
                #pragma unroll
                for (int j = 0; j < 4; j++) {
                    const float* bp = (const float*)&b4[j];
                    const float bs = bp[kk2];
                    const u64 bb = pack2(bs, bs);
                    fma2(acc[0][j], aA.x, bb);
                    fma2(acc[1][j], aA.y, bb);
                    fma2(acc[2][j], aB.x, bb);
                    fma2(acc[3][j], aB.y, bb);
                }
            }
        }
    }

    // ---- epilogue: (acc + bias[e,n]) * w[slot], scatter to out[slot, n] ----
    int   slot[8];
    float w8[8];
    #pragma unroll
    for (int t = 0; t < 8; t++) {
        slot[t] = g_slot[e * CAP + 8 * tc + t];
        w8[t]   = g_w  [e * CAP + 8 * tc + t];
    }
    float bv[4];
    #pragma unroll
    for (int j = 0; j < 4; j++)
        bv[j] = bias[e * NDIM + n0 + tn + 32 * j];

    #pragma unroll
    for (int p = 0; p < 4; p++) {
        #pragma unroll
        for (int j = 0; j < 4; j++) {
            float lo, hi;
            unpack2(acc[p][j], lo, hi);
            const int n = n0 + tn + 32 * j;
            out[(size_t)slot[2 * p]     * NDIM + n] = (lo + bv[j]) * w8[2 * p];
            out[(size_t)slot[2 * p + 1] * NDIM + n] = (hi + bv[j]) * w8[2 * p + 1];
        }
    }
}

extern "C" void kernel_launch(void* const* d_in, const int* in_sizes, int n_in,
                              void* d_out, int out_size) {
    const float* A    = (const float*)d_in[0];   // [256, 1024] f32
    const float* B    = (const float*)d_in[1];   // [64, 2048, 1024] f32
    const float* bias = (const float*)d_in[2];   // [64, 2048] f32
    const float* tw   = (const float*)d_in[3];   // [256, 8] f32
    const int*   ids  = (const int*)d_in[4];     // [256, 8] i32
    float* out = (float*)d_out;                  // [256, 8, 2048] f32

    (void)in_sizes; (void)n_in; (void)out_size;

    cudaFuncSetAttribute(moe_gemm_kernel,
                         cudaFuncAttributeMaxDynamicSharedMemorySize, SMEM_BYTES);

    route_kernel<<<NEXP, 32>>>(ids, tw);
    moe_gemm_kernel<<<NEXP * NTILES, NTHREADS, SMEM_BYTES>>>(A, B, bias, out);
}